// round 7
// baseline (speedup 1.0000x reference)
#include <cuda_runtime.h>
#include <cuda_bf16.h>
#include <cstdint>

#define BATCH 8
#define NPTS  4096
#define MPTS  4096
#define CDIM  128
#define TILE  128
#define INF_BITS 0x7F800000u

// ---------------- device scratch (no allocation allowed) -------------------
__device__ unsigned       g_rowmin[BATCH * NPTS];
__device__ unsigned       g_colmin[BATCH * MPTS];
__device__ float          g_norm1[BATCH * NPTS];
__device__ float          g_norm2[BATCH * MPTS];
__device__ __nv_bfloat16  g_bf1[BATCH * NPTS * CDIM];   // 8.4 MB
__device__ __nv_bfloat16  g_bf2[BATCH * MPTS * CDIM];   // 8.4 MB
__device__ float          g_partial[64];

// ---------------- PTX helpers (plain sm_80+ instructions only) -------------
__device__ __forceinline__ uint32_t smem_u32(const void* p) {
    uint32_t a;
    asm("{ .reg .u64 t; cvta.to.shared.u64 t, %1; cvt.u32.u64 %0, t; }" : "=r"(a) : "l"(p));
    return a;
}
__device__ __forceinline__ void ldmatrix_x4(uint32_t& r0, uint32_t& r1,
                                            uint32_t& r2, uint32_t& r3, uint32_t addr) {
    asm volatile("ldmatrix.sync.aligned.m8n8.x4.shared.b16 {%0,%1,%2,%3}, [%4];"
                 : "=r"(r0), "=r"(r1), "=r"(r2), "=r"(r3) : "r"(addr));
}
__device__ __forceinline__ void mma16816(float* d, const uint32_t* a,
                                         uint32_t b0, uint32_t b1) {
    asm volatile("mma.sync.aligned.m16n8k16.row.col.f32.bf16.bf16.f32 "
                 "{%0,%1,%2,%3}, {%4,%5,%6,%7}, {%8,%9}, {%0,%1,%2,%3};"
                 : "+f"(d[0]), "+f"(d[1]), "+f"(d[2]), "+f"(d[3])
                 : "r"(a[0]), "r"(a[1]), "r"(a[2]), "r"(a[3]), "r"(b0), "r"(b1));
}

// ---------------- kernel 1: fused fp32->bf16 convert + norm + min-init ------
// 8 threads per row; each thread handles 16 contiguous elements.
__global__ void prep_kernel(const float* __restrict__ s1, const float* __restrict__ s2) {
    const int total1 = BATCH * NPTS;
    int row = blockIdx.x * 32 + (threadIdx.x >> 3);   // 32 rows per block
    int sub = threadIdx.x & 7;
    const float* src;
    __nv_bfloat16* dst;
    int j;
    if (row < total1) { src = s1; dst = g_bf1; j = row; }
    else { src = s2; dst = g_bf2; j = row - total1; }
    const float* rp = src + (size_t)j * CDIM + sub * 16;
    __nv_bfloat16* wp = dst + (size_t)j * CDIM + sub * 16;

    float s = 0.f;
#pragma unroll
    for (int h = 0; h < 2; h++) {
        float4 a = *reinterpret_cast<const float4*>(rp + h * 8);
        float4 b = *reinterpret_cast<const float4*>(rp + h * 8 + 4);
        __nv_bfloat162 p0 = __floats2bfloat162_rn(a.x, a.y);
        __nv_bfloat162 p1 = __floats2bfloat162_rn(a.z, a.w);
        __nv_bfloat162 p2 = __floats2bfloat162_rn(b.x, b.y);
        __nv_bfloat162 p3 = __floats2bfloat162_rn(b.z, b.w);
        uint4 o;
        o.x = *reinterpret_cast<unsigned*>(&p0);
        o.y = *reinterpret_cast<unsigned*>(&p1);
        o.z = *reinterpret_cast<unsigned*>(&p2);
        o.w = *reinterpret_cast<unsigned*>(&p3);
        *reinterpret_cast<uint4*>(wp + h * 8) = o;
        // norm from the ROUNDED values (keeps d^2 = ||x̂-ŷ||^2 exact in bf16 space)
        float2 f0 = __bfloat1622float2(p0);
        float2 f1 = __bfloat1622float2(p1);
        float2 f2 = __bfloat1622float2(p2);
        float2 f3 = __bfloat1622float2(p3);
        s += f0.x * f0.x + f0.y * f0.y + f1.x * f1.x + f1.y * f1.y;
        s += f2.x * f2.x + f2.y * f2.y + f3.x * f3.x + f3.y * f3.y;
    }
    // reduce over the 8 lanes of this row (width-8 shfl)
    s += __shfl_down_sync(0xffffffffu, s, 4, 8);
    s += __shfl_down_sync(0xffffffffu, s, 2, 8);
    s += __shfl_down_sync(0xffffffffu, s, 1, 8);
    if (sub == 0) {
        if (row < total1) { g_norm1[j] = s; g_rowmin[j] = INF_BITS; }
        else              { g_norm2[j] = s; g_colmin[j] = INF_BITS; }
    }
}

// ---------------- kernel 2: mma.sync GEMM tile + min epilogue ----------------
static constexpr int SMEM_B_OFF  = 32768;
static constexpr int SMEM_N1     = 65536;
static constexpr int SMEM_N2     = 66048;
static constexpr int SMEM_RMIN   = 66560;
static constexpr int SMEM_CMIN   = 67072;
static constexpr int SMEM_TOTAL  = 67584;

__global__ __launch_bounds__(256, 2)
void chamfer_mma() {
    extern __shared__ char smem[];
    const uint32_t sb = smem_u32(smem);
    const int tid  = threadIdx.x;
    const int wid  = tid >> 5;
    const int lane = tid & 31;
    const int wr   = wid >> 2;
    const int wc   = wid & 3;
    const int bcol = blockIdx.x * TILE;
    const int brow = blockIdx.y * TILE;
    const int b    = blockIdx.z;

    float*    n1s    = reinterpret_cast<float*>(smem + SMEM_N1);
    float*    n2s    = reinterpret_cast<float*>(smem + SMEM_N2);
    unsigned* rmin_s = reinterpret_cast<unsigned*>(smem + SMEM_RMIN);
    unsigned* cmin_s = reinterpret_cast<unsigned*>(smem + SMEM_CMIN);

    const __nv_bfloat16* Ag = g_bf1 + ((size_t)b * NPTS + brow) * CDIM;
    const __nv_bfloat16* Bg = g_bf2 + ((size_t)b * MPTS + bcol) * CDIM;
#pragma unroll
    for (int it = 0; it < 8; it++) {
        int c = it * 256 + tid;
        int row = c >> 4, col16 = c & 15;
        int so = row * 256 + ((col16 ^ (row & 7)) << 4);
        *reinterpret_cast<uint4*>(smem + so) =
            *reinterpret_cast<const uint4*>(Ag + row * CDIM + col16 * 8);
        *reinterpret_cast<uint4*>(smem + SMEM_B_OFF + so) =
            *reinterpret_cast<const uint4*>(Bg + row * CDIM + col16 * 8);
    }
    if (tid < TILE) {
        n1s[tid] = g_norm1[b * NPTS + brow + tid];
        n2s[tid] = g_norm2[b * MPTS + bcol + tid];
        rmin_s[tid] = INF_BITS;
        cmin_s[tid] = INF_BITS;
    }
    __syncthreads();

    float acc[4][4][4] = {};
    const int m  = lane >> 3;
    const int li = lane & 7;
    const int ksel = m >> 1;

    uint32_t a_base[4], b_base[2];
#pragma unroll
    for (int mi = 0; mi < 4; mi++)
        a_base[mi] = sb + (wr * 64 + mi * 16 + (m & 1) * 8 + li) * 256;
#pragma unroll
    for (int nj2 = 0; nj2 < 2; nj2++)
        b_base[nj2] = sb + SMEM_B_OFF + (wc * 32 + nj2 * 16 + (m & 1) * 8 + li) * 256;

#pragma unroll
    for (int kk = 0; kk < 8; kk++) {
        const uint32_t xoff = (uint32_t)(((kk * 2 + ksel) ^ li) << 4);
        uint32_t af[4][4], bf[2][4];
#pragma unroll
        for (int mi = 0; mi < 4; mi++)
            ldmatrix_x4(af[mi][0], af[mi][1], af[mi][2], af[mi][3], a_base[mi] + xoff);
#pragma unroll
        for (int nj2 = 0; nj2 < 2; nj2++)
            ldmatrix_x4(bf[nj2][0], bf[nj2][1], bf[nj2][2], bf[nj2][3], b_base[nj2] + xoff);
#pragma unroll
        for (int mi = 0; mi < 4; mi++)
#pragma unroll
            for (int nj = 0; nj < 4; nj++)
                mma16816(acc[mi][nj], af[mi], bf[nj >> 1][nj & 1], bf[nj >> 1][2 + (nj & 1)]);
    }

    const float INF = __uint_as_float(INF_BITS);
    const int q = lane >> 2;
    const int s = lane & 3;

    float n2c[4][2], n1r[4][2];
#pragma unroll
    for (int nj = 0; nj < 4; nj++) {
        n2c[nj][0] = n2s[wc * 32 + nj * 8 + 2 * s];
        n2c[nj][1] = n2s[wc * 32 + nj * 8 + 2 * s + 1];
    }
#pragma unroll
    for (int mi = 0; mi < 4; mi++) {
        n1r[mi][0] = n1s[wr * 64 + mi * 16 + q];
        n1r[mi][1] = n1s[wr * 64 + mi * 16 + q + 8];
    }

    float colm[4][2];
#pragma unroll
    for (int nj = 0; nj < 4; nj++) { colm[nj][0] = INF; colm[nj][1] = INF; }

#pragma unroll
    for (int mi = 0; mi < 4; mi++) {
        float r0 = INF, r1 = INF;
#pragma unroll
        for (int nj = 0; nj < 4; nj++) {
            float d2a = fmaxf(n1r[mi][0] + n2c[nj][0] - 2.0f * acc[mi][nj][0], 0.0f);
            float d2b = fmaxf(n1r[mi][0] + n2c[nj][1] - 2.0f * acc[mi][nj][1], 0.0f);
            float d2c = fmaxf(n1r[mi][1] + n2c[nj][0] - 2.0f * acc[mi][nj][2], 0.0f);
            float d2d = fmaxf(n1r[mi][1] + n2c[nj][1] - 2.0f * acc[mi][nj][3], 0.0f);
            r0 = fminf(r0, fminf(d2a, d2b));
            r1 = fminf(r1, fminf(d2c, d2d));
            colm[nj][0] = fminf(colm[nj][0], fminf(d2a, d2c));
            colm[nj][1] = fminf(colm[nj][1], fminf(d2b, d2d));
        }
        r0 = fminf(r0, __shfl_xor_sync(0xffffffffu, r0, 1));
        r0 = fminf(r0, __shfl_xor_sync(0xffffffffu, r0, 2));
        r1 = fminf(r1, __shfl_xor_sync(0xffffffffu, r1, 1));
        r1 = fminf(r1, __shfl_xor_sync(0xffffffffu, r1, 2));
        if (s == 0) {
            atomicMin(&rmin_s[wr * 64 + mi * 16 + q],     __float_as_uint(r0));
            atomicMin(&rmin_s[wr * 64 + mi * 16 + q + 8], __float_as_uint(r1));
        }
    }
#pragma unroll
    for (int nj = 0; nj < 4; nj++) {
#pragma unroll
        for (int h = 0; h < 2; h++) {
            float v = colm[nj][h];
            v = fminf(v, __shfl_xor_sync(0xffffffffu, v, 4));
            v = fminf(v, __shfl_xor_sync(0xffffffffu, v, 8));
            v = fminf(v, __shfl_xor_sync(0xffffffffu, v, 16));
            if (q == 0)
                atomicMin(&cmin_s[wc * 32 + nj * 8 + 2 * s + h], __float_as_uint(v));
        }
    }
    __syncthreads();

    if (tid < TILE) {
        atomicMin(&g_rowmin[b * NPTS + brow + tid], rmin_s[tid]);
        atomicMin(&g_colmin[b * MPTS + bcol + tid], cmin_s[tid]);
    }
}

// ---------------- kernel 3a: parallel partial reduction (deterministic) -----
// 64 blocks x 1024 elements = 65536 = 2 * 32768 (rowmin then colmin). In-bounds.
__global__ void reduce_stage1(const float* __restrict__ w1,
                              const float* __restrict__ w2) {
    __shared__ float red[256];
    const int t = threadIdx.x;
    const int bid = blockIdx.x;            // 0..63
    const int total1 = BATCH * NPTS;       // 32768
    float s = 0.0f;
#pragma unroll
    for (int k = 0; k < 4; k++) {
        int idx = bid * 1024 + k * 256 + t; // 0 .. 65535
        if (idx < total1) {
            s += w1[idx] * sqrtf(__uint_as_float(g_rowmin[idx]));
        } else {
            int j = idx - total1;           // 0 .. 32767
            s += w2[j] * sqrtf(__uint_as_float(g_colmin[j]));
        }
    }
    red[t] = s;
    __syncthreads();
    for (int o = 128; o > 0; o >>= 1) {
        if (t < o) red[t] += red[t + o];
        __syncthreads();
    }
    if (t == 0) g_partial[bid] = red[0];
}

// ---------------- kernel 3b: final sum ---------------------------------------
__global__ void reduce_stage2(float* __restrict__ out) {
    __shared__ float red[64];
    int t = threadIdx.x;                   // 64 threads
    red[t] = g_partial[t];
    __syncthreads();
    for (int o = 32; o > 0; o >>= 1) {
        if (t < o) red[t] += red[t + o];
        __syncthreads();
    }
    if (t == 0) out[0] = red[0] * 0.5f;
}

// ---------------------------------------------------------------------------
extern "C" void kernel_launch(void* const* d_in, const int* in_sizes, int n_in,
                              void* d_out, int out_size) {
    const float* set1 = (const float*)d_in[0];
    const float* set2 = (const float*)d_in[1];
    const float* w1   = (const float*)d_in[2];
    const float* w2   = (const float*)d_in[3];
    float* out = (float*)d_out;
    (void)in_sizes; (void)n_in; (void)out_size;

    static bool attr_done = false;
    if (!attr_done) {
        cudaFuncSetAttribute(chamfer_mma, cudaFuncAttributeMaxDynamicSharedMemorySize, SMEM_TOTAL);
        attr_done = true;
    }

    // 1) fused convert + norms + min-init: 65536 rows, 32 rows/block
    prep_kernel<<<2 * BATCH * NPTS / 32, 256>>>(set1, set2);
    // 2) main GEMM + mins
    dim3 grid(MPTS / TILE, NPTS / TILE, BATCH);
    chamfer_mma<<<grid, 256, SMEM_TOTAL>>>();
    // 3) deterministic two-stage weighted reduction (65536 elements total)
    reduce_stage1<<<64, 256>>>(w1, w2);
    reduce_stage2<<<1, 64>>>(out);
}

// round 8
// speedup vs baseline: 1.0900x; 1.0900x over previous
#include <cuda_runtime.h>
#include <cuda_bf16.h>
#include <cstdint>

#define BATCH 8
#define NPTS  4096
#define MPTS  4096
#define CDIM  128
#define TILE  128
#define STRIP 8          // B tiles per CTA (along columns)
#define INF_BITS 0x7F800000u

// ---------------- device scratch (no allocation allowed) -------------------
__device__ unsigned       g_rowmin[BATCH * NPTS];
__device__ unsigned       g_colmin[BATCH * MPTS];
__device__ float          g_norm1[BATCH * NPTS];
__device__ float          g_norm2[BATCH * MPTS];
__device__ __nv_bfloat16  g_bf1[BATCH * NPTS * CDIM];   // holds -2*x_hat
__device__ __nv_bfloat16  g_bf2[BATCH * MPTS * CDIM];   // holds  y_hat
__device__ float          g_partial[64];
__device__ unsigned       g_done;

// ---------------- PTX helpers (plain sm_80+ instructions only) -------------
__device__ __forceinline__ uint32_t smem_u32(const void* p) {
    uint32_t a;
    asm("{ .reg .u64 t; cvta.to.shared.u64 t, %1; cvt.u32.u64 %0, t; }" : "=r"(a) : "l"(p));
    return a;
}
__device__ __forceinline__ void ldmatrix_x4(uint32_t& r0, uint32_t& r1,
                                            uint32_t& r2, uint32_t& r3, uint32_t addr) {
    asm volatile("ldmatrix.sync.aligned.m8n8.x4.shared.b16 {%0,%1,%2,%3}, [%4];"
                 : "=r"(r0), "=r"(r1), "=r"(r2), "=r"(r3) : "r"(addr));
}
__device__ __forceinline__ void mma16816(float* d, const uint32_t* a,
                                         uint32_t b0, uint32_t b1) {
    asm volatile("mma.sync.aligned.m16n8k16.row.col.f32.bf16.bf16.f32 "
                 "{%0,%1,%2,%3}, {%4,%5,%6,%7}, {%8,%9}, {%0,%1,%2,%3};"
                 : "+f"(d[0]), "+f"(d[1]), "+f"(d[2]), "+f"(d[3])
                 : "r"(a[0]), "r"(a[1]), "r"(a[2]), "r"(a[3]), "r"(b0), "r"(b1));
}
#define CP_ASYNC16(dst, src) \
    asm volatile("cp.async.cg.shared.global [%0], [%1], 16;" :: "r"(dst), "l"(src))
#define CP_COMMIT() asm volatile("cp.async.commit_group;" ::: "memory")
#define CP_WAIT0()  asm volatile("cp.async.wait_group 0;" ::: "memory")

// ---------------- kernel 1: fused convert + norm + min-init + counter -------
// set1 stored as -2 * rn(x) (exact scaling); norm1 = ||rn(x)||^2 = 0.25*sum(stored^2)
__global__ void prep_kernel(const float* __restrict__ s1, const float* __restrict__ s2) {
    if (blockIdx.x == 0 && threadIdx.x == 0) g_done = 0;
    const int total1 = BATCH * NPTS;
    int row = blockIdx.x * 32 + (threadIdx.x >> 3);
    int sub = threadIdx.x & 7;
    bool isA = row < total1;
    const float* src;
    __nv_bfloat16* dst;
    int j;
    if (isA) { src = s1; dst = g_bf1; j = row; }
    else     { src = s2; dst = g_bf2; j = row - total1; }
    const float mul = isA ? -2.0f : 1.0f;
    const float* rp = src + (size_t)j * CDIM + sub * 16;
    __nv_bfloat16* wp = dst + (size_t)j * CDIM + sub * 16;

    float s = 0.f;
#pragma unroll
    for (int h = 0; h < 2; h++) {
        float4 a = *reinterpret_cast<const float4*>(rp + h * 8);
        float4 b = *reinterpret_cast<const float4*>(rp + h * 8 + 4);
        __nv_bfloat162 p0 = __floats2bfloat162_rn(mul * a.x, mul * a.y);
        __nv_bfloat162 p1 = __floats2bfloat162_rn(mul * a.z, mul * a.w);
        __nv_bfloat162 p2 = __floats2bfloat162_rn(mul * b.x, mul * b.y);
        __nv_bfloat162 p3 = __floats2bfloat162_rn(mul * b.z, mul * b.w);
        uint4 o;
        o.x = *reinterpret_cast<unsigned*>(&p0);
        o.y = *reinterpret_cast<unsigned*>(&p1);
        o.z = *reinterpret_cast<unsigned*>(&p2);
        o.w = *reinterpret_cast<unsigned*>(&p3);
        *reinterpret_cast<uint4*>(wp + h * 8) = o;
        float2 f0 = __bfloat1622float2(p0);
        float2 f1 = __bfloat1622float2(p1);
        float2 f2 = __bfloat1622float2(p2);
        float2 f3 = __bfloat1622float2(p3);
        s += f0.x * f0.x + f0.y * f0.y + f1.x * f1.x + f1.y * f1.y;
        s += f2.x * f2.x + f2.y * f2.y + f3.x * f3.x + f3.y * f3.y;
    }
    s += __shfl_down_sync(0xffffffffu, s, 4, 8);
    s += __shfl_down_sync(0xffffffffu, s, 2, 8);
    s += __shfl_down_sync(0xffffffffu, s, 1, 8);
    if (sub == 0) {
        if (isA) { g_norm1[j] = 0.25f * s; g_rowmin[j] = INF_BITS; }
        else     { g_norm2[j] = s;         g_colmin[j] = INF_BITS; }
    }
}

// ---------------- kernel 2: strip-persistent mma GEMM + min epilogue --------
static constexpr int SMEM_A_OFF  = 0;          // 32 KB (A resident for strip)
static constexpr int SMEM_B0_OFF = 32768;      // 32 KB
static constexpr int SMEM_B1_OFF = 65536;      // 32 KB
static constexpr int SMEM_N1     = 98304;      // 128 f32
static constexpr int SMEM_N2     = 98816;      // 128 f32
static constexpr int SMEM_RMIN   = 99328;      // 128 u32
static constexpr int SMEM_CMIN   = 99840;      // 128 u32
static constexpr int SMEM_TOTAL  = 100352;

__global__ __launch_bounds__(256, 2)
void chamfer_mma() {
    extern __shared__ char smem[];
    const uint32_t sb = smem_u32(smem);
    const int tid  = threadIdx.x;
    const int wid  = tid >> 5;
    const int lane = tid & 31;
    const int wr   = wid >> 2;        // 0..1 (64 rows)
    const int wc   = wid & 3;         // 0..3 (32 cols)
    const int brow  = blockIdx.y * TILE;
    const int bcol0 = blockIdx.x * (TILE * STRIP);
    const int b     = blockIdx.z;

    float*    n1s    = reinterpret_cast<float*>(smem + SMEM_N1);
    float*    n2s    = reinterpret_cast<float*>(smem + SMEM_N2);
    unsigned* rmin_s = reinterpret_cast<unsigned*>(smem + SMEM_RMIN);
    unsigned* cmin_s = reinterpret_cast<unsigned*>(smem + SMEM_CMIN);

    const __nv_bfloat16* Ag  = g_bf1 + ((size_t)b * NPTS + brow) * CDIM;
    const __nv_bfloat16* Bg0 = g_bf2 + ((size_t)b * MPTS + bcol0) * CDIM;

    // ---- prologue: async-load A tile + B tile 0 (one commit group) ----
#pragma unroll
    for (int p = 0; p < 8; p++) {
        int c = p * 256 + tid;
        int row = c >> 4, col16 = c & 15;
        uint32_t so = row * 256 + ((col16 ^ (row & 7)) << 4);
        CP_ASYNC16(sb + SMEM_A_OFF + so,  Ag  + row * CDIM + col16 * 8);
    }
#pragma unroll
    for (int p = 0; p < 8; p++) {
        int c = p * 256 + tid;
        int row = c >> 4, col16 = c & 15;
        uint32_t so = row * 256 + ((col16 ^ (row & 7)) << 4);
        CP_ASYNC16(sb + SMEM_B0_OFF + so, Bg0 + row * CDIM + col16 * 8);
    }
    CP_COMMIT();
    if (tid < TILE) {
        n1s[tid] = g_norm1[b * NPTS + brow + tid];
        rmin_s[tid] = INF_BITS;
    }

    // thread geometry inside warp
    const int m  = lane >> 3;
    const int li = lane & 7;
    const int ksel = m >> 1;
    const int q = lane >> 2;
    const int s = lane & 3;
    const float INF = __uint_as_float(INF_BITS);

    uint32_t a_base[4];
#pragma unroll
    for (int mi = 0; mi < 4; mi++)
        a_base[mi] = sb + SMEM_A_OFF + (wr * 64 + mi * 16 + (m & 1) * 8 + li) * 256;

    float n1r[4][2];
    float rowm[4][2];
#pragma unroll
    for (int mi = 0; mi < 4; mi++) { rowm[mi][0] = INF; rowm[mi][1] = INF; }

    for (int it = 0; it < STRIP; it++) {
        CP_WAIT0();
        __syncthreads();

        // prefetch next B tile into the other buffer (overlaps mainloop)
        if (it + 1 < STRIP) {
            const __nv_bfloat16* Bn = Bg0 + (size_t)(it + 1) * TILE * CDIM;
            uint32_t dstb = sb + ((it + 1) & 1 ? SMEM_B1_OFF : SMEM_B0_OFF);
#pragma unroll
            for (int p = 0; p < 8; p++) {
                int c = p * 256 + tid;
                int row = c >> 4, col16 = c & 15;
                uint32_t so = row * 256 + ((col16 ^ (row & 7)) << 4);
                CP_ASYNC16(dstb + so, Bn + row * CDIM + col16 * 8);
            }
            CP_COMMIT();
        }
        if (tid < TILE) {
            n2s[tid] = g_norm2[b * MPTS + bcol0 + it * TILE + tid];
            cmin_s[tid] = INF_BITS;
        }
        if (it == 0) {
#pragma unroll
            for (int mi = 0; mi < 4; mi++) {
                n1r[mi][0] = n1s[wr * 64 + mi * 16 + q];
                n1r[mi][1] = n1s[wr * 64 + mi * 16 + q + 8];
            }
        }

        // ---- mainloop on buffer it&1 ----
        const uint32_t sbB = sb + ((it & 1) ? SMEM_B1_OFF : SMEM_B0_OFF);
        uint32_t b_base[2];
#pragma unroll
        for (int nj2 = 0; nj2 < 2; nj2++)
            b_base[nj2] = sbB + (wc * 32 + nj2 * 16 + (m & 1) * 8 + li) * 256;

        float acc[4][4][4];
#pragma unroll
        for (int mi = 0; mi < 4; mi++)
#pragma unroll
            for (int nj = 0; nj < 4; nj++)
#pragma unroll
                for (int e = 0; e < 4; e++) acc[mi][nj][e] = 0.f;

#pragma unroll
        for (int kk = 0; kk < 8; kk++) {
            const uint32_t xoff = (uint32_t)(((kk * 2 + ksel) ^ li) << 4);
            uint32_t af[4][4], bf[2][4];
#pragma unroll
            for (int mi = 0; mi < 4; mi++)
                ldmatrix_x4(af[mi][0], af[mi][1], af[mi][2], af[mi][3], a_base[mi] + xoff);
#pragma unroll
            for (int nj2 = 0; nj2 < 2; nj2++)
                ldmatrix_x4(bf[nj2][0], bf[nj2][1], bf[nj2][2], bf[nj2][3], b_base[nj2] + xoff);
#pragma unroll
            for (int mi = 0; mi < 4; mi++)
#pragma unroll
                for (int nj = 0; nj < 4; nj++)
                    mma16816(acc[mi][nj], af[mi], bf[nj >> 1][nj & 1], bf[nj >> 1][2 + (nj & 1)]);
        }
        __syncthreads();   // mainloop done; n2s/cmin ready

        // ---- epilogue: acc = -2*dot. rowm folds (n2+t); colm folds (n1+t) ----
        float n2c[4][2];
#pragma unroll
        for (int nj = 0; nj < 4; nj++) {
            n2c[nj][0] = n2s[wc * 32 + nj * 8 + 2 * s];
            n2c[nj][1] = n2s[wc * 32 + nj * 8 + 2 * s + 1];
        }
        float colm[4][2];
#pragma unroll
        for (int nj = 0; nj < 4; nj++) { colm[nj][0] = INF; colm[nj][1] = INF; }

#pragma unroll
        for (int mi = 0; mi < 4; mi++) {
#pragma unroll
            for (int nj = 0; nj < 4; nj++) {
                const float* a = acc[mi][nj];
                rowm[mi][0] = fminf(rowm[mi][0], a[0] + n2c[nj][0]);
                rowm[mi][0] = fminf(rowm[mi][0], a[1] + n2c[nj][1]);
                rowm[mi][1] = fminf(rowm[mi][1], a[2] + n2c[nj][0]);
                rowm[mi][1] = fminf(rowm[mi][1], a[3] + n2c[nj][1]);
                colm[nj][0] = fminf(colm[nj][0], a[0] + n1r[mi][0]);
                colm[nj][1] = fminf(colm[nj][1], a[1] + n1r[mi][0]);
                colm[nj][0] = fminf(colm[nj][0], a[2] + n1r[mi][1]);
                colm[nj][1] = fminf(colm[nj][1], a[3] + n1r[mi][1]);
            }
        }
        // column reduce across the 8 q-lanes, add n2, clamp, smem atomic
#pragma unroll
        for (int nj = 0; nj < 4; nj++) {
#pragma unroll
            for (int h = 0; h < 2; h++) {
                float v = colm[nj][h];
                v = fminf(v, __shfl_xor_sync(0xffffffffu, v, 4));
                v = fminf(v, __shfl_xor_sync(0xffffffffu, v, 8));
                v = fminf(v, __shfl_xor_sync(0xffffffffu, v, 16));
                if (q == 0) {
                    float d2 = fmaxf(v + n2c[nj][h], 0.0f);
                    atomicMin(&cmin_s[wc * 32 + nj * 8 + 2 * s + h], __float_as_uint(d2));
                }
            }
        }
        __syncthreads();
        if (tid < TILE)
            atomicMin(&g_colmin[b * MPTS + bcol0 + it * TILE + tid], cmin_s[tid]);
    }

    // ---- strip end: row reduce across the 4 s-lanes, add n1, clamp ----
#pragma unroll
    for (int mi = 0; mi < 4; mi++) {
#pragma unroll
        for (int h = 0; h < 2; h++) {
            float v = rowm[mi][h];
            v = fminf(v, __shfl_xor_sync(0xffffffffu, v, 1));
            v = fminf(v, __shfl_xor_sync(0xffffffffu, v, 2));
            if (s == 0) {
                float d2 = fmaxf(v + n1r[mi][h], 0.0f);
                atomicMin(&rmin_s[wr * 64 + mi * 16 + q + h * 8], __float_as_uint(d2));
            }
        }
    }
    __syncthreads();
    if (tid < TILE)
        atomicMin(&g_rowmin[b * NPTS + brow + tid], rmin_s[tid]);
}

// ---------------- kernel 3: fused deterministic weighted reduction ----------
__global__ void reduce_all(const float* __restrict__ w1,
                           const float* __restrict__ w2,
                           float* __restrict__ out) {
    __shared__ float red[256];
    __shared__ unsigned slast;
    const int t = threadIdx.x;
    const int bid = blockIdx.x;            // 0..63
    const int total1 = BATCH * NPTS;       // 32768
    float sum = 0.0f;
#pragma unroll
    for (int k = 0; k < 4; k++) {
        int idx = bid * 1024 + k * 256 + t; // 0 .. 65535
        if (idx < total1)
            sum += w1[idx] * sqrtf(__uint_as_float(g_rowmin[idx]));
        else {
            int j = idx - total1;           // 0 .. 32767
            sum += w2[j] * sqrtf(__uint_as_float(g_colmin[j]));
        }
    }
    red[t] = sum;
    __syncthreads();
    for (int o = 128; o > 0; o >>= 1) {
        if (t < o) red[t] += red[t + o];
        __syncthreads();
    }
    if (t == 0) {
        g_partial[bid] = red[0];
        __threadfence();
        unsigned prev = atomicAdd(&g_done, 1u);
        slast = (prev == 63u) ? 1u : 0u;
    }
    __syncthreads();
    if (slast) {
        // last block: deterministic fixed-order final sum of 64 partials
        volatile float* gp = g_partial;
        if (t < 64) red[t] = gp[t];
        __syncthreads();
        for (int o = 32; o > 0; o >>= 1) {
            if (t < o) red[t] += red[t + o];
            __syncthreads();
        }
        if (t == 0) out[0] = red[0] * 0.5f;
    }
}

// ---------------------------------------------------------------------------
extern "C" void kernel_launch(void* const* d_in, const int* in_sizes, int n_in,
                              void* d_out, int out_size) {
    const float* set1 = (const float*)d_in[0];
    const float* set2 = (const float*)d_in[1];
    const float* w1   = (const float*)d_in[2];
    const float* w2   = (const float*)d_in[3];
    float* out = (float*)d_out;
    (void)in_sizes; (void)n_in; (void)out_size;

    static bool attr_done = false;
    if (!attr_done) {
        cudaFuncSetAttribute(chamfer_mma, cudaFuncAttributeMaxDynamicSharedMemorySize, SMEM_TOTAL);
        attr_done = true;
    }

    prep_kernel<<<2 * BATCH * NPTS / 32, 256>>>(set1, set2);
    dim3 grid(MPTS / (TILE * STRIP), NPTS / TILE, BATCH);
    chamfer_mma<<<grid, 256, SMEM_TOTAL>>>();
    reduce_all<<<64, 256>>>(w1, w2, out);
}